// round 12
// baseline (speedup 1.0000x reference)
#include <cuda_runtime.h>
#include <cstdint>

// R12: AR(24) rollout as a fully closed-form affine map (no recurrence in the
// hot loop). y[t] = M[t]·win0 + C[t]*b, M[168][24] built by a FAST prep
// kernel using the polynomial shift recurrence
//     row_{t+1}[k] = row_t[k-1] + row_t[23]*W[k]   (depth-1 FMA per step)
//     beta_{t+1}   = beta_t + row_t[23]            (bias column, running sum)
// (x^{t+1} mod characteristic polynomial; verified vs direct expansion).
// Main kernel: one thread = two adjacent d channels; win0 read-only in regs;
// coefficients dup-packed in SMEM consumed via broadcast LDS.128 feeding
// packed fma.rn.f32x2. All 168 outputs independent -> unlimited ILP, no
// serial chain, no spill candidates (~60 regs).
//
// Shapes: x [256,336,512] f32, W [24,1] f32, b [1] f32, out [256,168,512] f32

#define ORDER 24
#define T_OUT 168
#define D_DIM 512
#define B_DIM 256
#define S_DIM 336
#define HALF_D (D_DIM / 2)
#define BLOCK 128

__device__ unsigned long long d_M2[T_OUT * ORDER];  // dup-packed M[t][k]
__device__ unsigned long long d_C2[T_OUT];          // dup-packed beta[t]*bias

static __device__ __forceinline__ unsigned long long dup_pack(float v) {
    unsigned int u = __float_as_uint(v);
    return ((unsigned long long)u << 32) | (unsigned long long)u;
}

// ---- prep: one warp. All lanes redundantly hold the current row in static
// registers (depth-1 update, no shuffles); lane k<24 stores element k,
// lane 24 stores the bias coefficient. ~168*30 cycles total.
__global__ void ar_prep_kernel(const float* __restrict__ W,
                               const float* __restrict__ bias) {
    const int lane = threadIdx.x;
    const float bval = __ldg(bias);

    float w[ORDER], c[ORDER];
#pragma unroll
    for (int k = 0; k < ORDER; k++) { w[k] = __ldg(&W[k]); c[k] = w[k]; }
    float beta = 1.0f;

    for (int t = 0; t < T_OUT; t++) {
        // store row t
        if (lane < ORDER)       d_M2[t * ORDER + lane] = dup_pack(c[lane]);
        else if (lane == ORDER) d_C2[t] = dup_pack(beta * bval);
        // advance: row_{t+1}[k] = row_t[k-1] + c23*w[k];  beta += c23
        float c23 = c[ORDER - 1];
#pragma unroll
        for (int k = ORDER - 1; k >= 1; k--) c[k] = fmaf(c23, w[k], c[k - 1]);
        c[0] = c23 * w[0];
        beta += c23;
    }
}

// ---- main: 65536 threads, one thread = two adjacent d channels.
__global__ __launch_bounds__(BLOCK)
void ar_matvec_kernel(const float* __restrict__ x,
                      float* __restrict__ out) {
    __shared__ __align__(16) unsigned long long M2s[T_OUT * ORDER];
    __shared__ __align__(16) unsigned long long C2s[T_OUT];

    const int tid = threadIdx.x;
    for (int idx = tid; idx < T_OUT * ORDER; idx += BLOCK) M2s[idx] = d_M2[idx];
    for (int idx = tid; idx < T_OUT; idx += BLOCK)         C2s[idx] = d_C2[idx];

    const int p = blockIdx.x * BLOCK + tid;   // pair index in [0, B*HALF_D)
    const int b = p / HALF_D;
    const int d = (p - b * HALF_D) * 2;

    // seed window: last ORDER timesteps, read-only for the whole kernel.
    unsigned long long win[ORDER];
    const float* xp = x + (size_t)b * S_DIM * D_DIM
                        + (size_t)(S_DIM - ORDER) * D_DIM + d;
#pragma unroll
    for (int k = 0; k < ORDER; k++)
        win[k] = *reinterpret_cast<const unsigned long long*>(xp + (size_t)k * D_DIM);

    __syncthreads();

    unsigned int m2_addr, c2_addr;
    asm("{ .reg .u64 t; cvta.to.shared.u64 t, %1; cvt.u32.u64 %0, t; }"
        : "=r"(m2_addr) : "l"(M2s));
    asm("{ .reg .u64 t; cvta.to.shared.u64 t, %1; cvt.u32.u64 %0, t; }"
        : "=r"(c2_addr) : "l"(C2s));

    float* op = out + (size_t)b * T_OUT * D_DIM + d;

    // 168 independent dot-products; 2 in flight per iteration.
#pragma unroll 1
    for (int t = 0; t < T_OUT; t += 2) {
        unsigned long long acc0, acc1;
        asm("ld.shared.v2.b64 {%0, %1}, [%2];"
            : "=l"(acc0), "=l"(acc1) : "r"(c2_addr + 8u * t));
#pragma unroll
        for (int j = 0; j < ORDER / 2; j++) {
            unsigned long long c0, c1, e0, e1;
            asm("ld.shared.v2.b64 {%0, %1}, [%2];"
                : "=l"(c0), "=l"(c1)
                : "r"(m2_addr + (unsigned)(t * ORDER * 8 + 16 * j)));
            asm("ld.shared.v2.b64 {%0, %1}, [%2];"
                : "=l"(e0), "=l"(e1)
                : "r"(m2_addr + (unsigned)((t + 1) * ORDER * 8 + 16 * j)));
            asm("fma.rn.f32x2 %0, %1, %2, %0;" : "+l"(acc0)
                : "l"(c0), "l"(win[2 * j]));
            asm("fma.rn.f32x2 %0, %1, %2, %0;" : "+l"(acc1)
                : "l"(e0), "l"(win[2 * j]));
            asm("fma.rn.f32x2 %0, %1, %2, %0;" : "+l"(acc0)
                : "l"(c1), "l"(win[2 * j + 1]));
            asm("fma.rn.f32x2 %0, %1, %2, %0;" : "+l"(acc1)
                : "l"(e1), "l"(win[2 * j + 1]));
        }
        *reinterpret_cast<unsigned long long*>(op + (size_t)t * D_DIM)       = acc0;
        *reinterpret_cast<unsigned long long*>(op + (size_t)(t + 1) * D_DIM) = acc1;
    }
}

extern "C" void kernel_launch(void* const* d_in, const int* in_sizes, int n_in,
                              void* d_out, int out_size) {
    const float* x  = (const float*)d_in[0];   // [256, 336, 512]
    const float* W  = (const float*)d_in[1];   // [24, 1]
    const float* bs = (const float*)d_in[2];   // [1]
    float* out = (float*)d_out;                // [256, 168, 512]

    ar_prep_kernel<<<1, 32>>>(W, bs);
    const int n_threads = B_DIM * HALF_D;      // 65536
    ar_matvec_kernel<<<n_threads / BLOCK, BLOCK>>>(x, out);
}

// round 14
// speedup vs baseline: 1.0873x; 1.0873x over previous
#include <cuda_runtime.h>
#include <cuda_bf16.h>
#include <cstdint>

// R14: AR(24) rollout as closed-form GEMM on Ampere-path tensor cores
// (mma.sync.m16n8k16 bf16 -> f32, baseline PTX: compiles for plain sm_103;
// tcgen05 is blocked because the harness targets compute_103 without 'a').
//   Y[row, t] = sum_k A[row, k] * B[k][t],  row=(b,d), K padded 24->32,
//   A[:,24]=1.0 and B[24][t]=beta_t*bias -> bias folded into the GEMM.
// Precision: split-bf16 3-MMA (AhiBhi + AhiBlo + AloBhi, fp32 accum) ~1e-5.
// Scalar FFMA2 paths are RF-banking capped (rt=3 => ~23us); tensor path is
// bound by the 88MB coalesced store stream (~11-15us).
//
// Shapes: x [256,336,512] f32, W [24,1] f32, b [1] f32, out [256,168,512] f32

#define ORDER 24
#define KPAD  32
#define T_OUT 168
#define D_DIM 512
#define B_DIM 256
#define S_DIM 336

#define CTA_ROWS 64
#define THREADS  128          // 4 warps; warp w owns rows w*16..w*16+15
#define KP 40                 // padded k-stride (bf16) for As/Bs: bank-safe
#define CP 173                // padded t-stride (f32) for Cs: 173%32=13, odd

#define AS_LO (CTA_ROWS * KP)             // 2560 bf16
#define BS_LO (T_OUT * KP)                // 6720 bf16
#define SM_BS_OFF 10240                   // bytes: after As hi+lo
#define SM_BYTES  44288                   // max(As+Bs=37120, Cs=64*173*4)

__device__ __nv_bfloat16 d_Bhi[T_OUT * KPAD];
__device__ __nv_bfloat16 d_Blo[T_OUT * KPAD];

// ---- prep (1 warp): lane k<24 owns coefficient column k via shfl recurrence
//   row0 = W;  m_k <- m_{k-1} + m_23*W[k] (m_0 <- m_23*W[0]);  beta += m_23
// (identical algebra to the R12 prep that PASSED with rel_err 2.2e-7).
__global__ void ar_prep_kernel(const float* __restrict__ W,
                               const float* __restrict__ bias) {
    const int lane = threadIdx.x;
    const float bval = __ldg(bias);
    const float wlane = (lane < ORDER) ? __ldg(&W[lane]) : 0.0f;
    float m = wlane;
    float beta = 1.0f;

    for (int t = 0; t < T_OUT; t++) {
        float c23 = __shfl_sync(0xFFFFFFFFu, m, ORDER - 1);
        float up  = __shfl_up_sync(0xFFFFFFFFu, m, 1);
        float v;
        if (lane < ORDER)       v = m;
        else if (lane == ORDER) v = beta * bval;
        else                    v = 0.0f;
        __nv_bfloat16 hi = __float2bfloat16(v);
        __nv_bfloat16 lo = __float2bfloat16(v - __bfloat162float(hi));
        d_Bhi[t * KPAD + lane] = hi;
        d_Blo[t * KPAD + lane] = lo;
        if (lane < ORDER) m = fmaf(c23, wlane, (lane == 0) ? 0.0f : up);
        if (lane == ORDER) beta += c23;
    }
}

#define MMA_BF16(c, A, B)                                                     \
    asm("mma.sync.aligned.m16n8k16.row.col.f32.bf16.bf16.f32 "                \
        "{%0,%1,%2,%3},{%4,%5,%6,%7},{%8,%9},{%0,%1,%2,%3};"                  \
        : "+f"((c)[0]), "+f"((c)[1]), "+f"((c)[2]), "+f"((c)[3])              \
        : "r"((A)[0]), "r"((A)[1]), "r"((A)[2]), "r"((A)[3]),                 \
          "r"((B)[0]), "r"((B)[1]))

__global__ void ar_mma_kernel(const float* __restrict__ x,
                              float* __restrict__ out) {
    __shared__ __align__(16) char sm[SM_BYTES];
    __nv_bfloat16* As = reinterpret_cast<__nv_bfloat16*>(sm);            // hi, then lo at AS_LO
    __nv_bfloat16* Bs = reinterpret_cast<__nv_bfloat16*>(sm + SM_BS_OFF); // hi, then lo at BS_LO
    float* Cs = reinterpret_cast<float*>(sm);                             // overlay after MMA

    const int tid = threadIdx.x;
    const int row0 = blockIdx.x * CTA_ROWS;
    const int b  = row0 >> 9;
    const int d0 = row0 & (D_DIM - 1);

    // --- stage A: window x[b, 312+k, d0+i], split bf16 hi/lo (coalesced in i)
    const float* xw = x + ((size_t)b * S_DIM + (S_DIM - ORDER)) * D_DIM + d0;
    for (int idx = tid; idx < ORDER * CTA_ROWS; idx += THREADS) {
        int k = idx >> 6, i = idx & 63;
        float v = __ldg(xw + (size_t)k * D_DIM + i);
        __nv_bfloat16 hi = __float2bfloat16(v);
        __nv_bfloat16 lo = __float2bfloat16(v - __bfloat162float(hi));
        As[i * KP + k] = hi;
        As[AS_LO + i * KP + k] = lo;
    }
    // bias column (k=24 -> 1.0) and zero pad k=25..31
    for (int idx = tid; idx < CTA_ROWS * (KPAD - ORDER); idx += THREADS) {
        int i = idx & 63, k = ORDER + (idx >> 6);
        As[i * KP + k] = __float2bfloat16((k == ORDER) ? 1.0f : 0.0f);
        As[AS_LO + i * KP + k] = __float2bfloat16(0.0f);
    }
    // --- stage B coefficients
    for (int idx = tid; idx < T_OUT * KPAD; idx += THREADS) {
        int t = idx >> 5, k = idx & 31;
        Bs[t * KP + k] = d_Bhi[idx];
        Bs[BS_LO + t * KP + k] = d_Blo[idx];
    }
    __syncthreads();

    const int wid = tid >> 5, lane = tid & 31;
    const int grp = lane >> 2, qp = lane & 3;
    const int r = wid * 16 + grp;

    // --- A fragments (nt-invariant): [split][kstep][4 regs]
    uint32_t a[2][2][4];
#pragma unroll
    for (int s = 0; s < 2; s++) {
        const int base = s ? AS_LO : 0;
#pragma unroll
        for (int ks = 0; ks < 2; ks++) {
            const int kb = ks * 16 + qp * 2;
            a[s][ks][0] = *reinterpret_cast<const uint32_t*>(&As[base + r * KP + kb]);
            a[s][ks][1] = *reinterpret_cast<const uint32_t*>(&As[base + (r + 8) * KP + kb]);
            a[s][ks][2] = *reinterpret_cast<const uint32_t*>(&As[base + r * KP + kb + 8]);
            a[s][ks][3] = *reinterpret_cast<const uint32_t*>(&As[base + (r + 8) * KP + kb + 8]);
        }
    }

    // --- 21 n-tiles x (2 ksteps x 3 split-MMAs); fp32 accums in registers
    float acc[21][4];
#pragma unroll
    for (int nt = 0; nt < 21; nt++)
#pragma unroll
        for (int c = 0; c < 4; c++) acc[nt][c] = 0.0f;

#pragma unroll
    for (int nt = 0; nt < 21; nt++) {
        const int t = nt * 8 + grp;
        uint32_t bh[2][2], bl[2][2];
#pragma unroll
        for (int ks = 0; ks < 2; ks++) {
            const int kb = ks * 16 + qp * 2;
            bh[ks][0] = *reinterpret_cast<const uint32_t*>(&Bs[t * KP + kb]);
            bh[ks][1] = *reinterpret_cast<const uint32_t*>(&Bs[t * KP + kb + 8]);
            bl[ks][0] = *reinterpret_cast<const uint32_t*>(&Bs[BS_LO + t * KP + kb]);
            bl[ks][1] = *reinterpret_cast<const uint32_t*>(&Bs[BS_LO + t * KP + kb + 8]);
        }
#pragma unroll
        for (int ks = 0; ks < 2; ks++) {
            MMA_BF16(acc[nt], a[0][ks], bh[ks]);   // hi*hi
            MMA_BF16(acc[nt], a[0][ks], bl[ks]);   // hi*lo
            MMA_BF16(acc[nt], a[1][ks], bh[ks]);   // lo*hi
        }
    }

    __syncthreads();   // everyone done reading As/Bs before Cs overlay

    // --- C fragments -> SMEM [row=d][t] (pad 173 -> conflict-free col reads)
#pragma unroll
    for (int nt = 0; nt < 21; nt++) {
        const int n = nt * 8 + qp * 2;
        Cs[r * CP + n]           = acc[nt][0];
        Cs[r * CP + n + 1]       = acc[nt][1];
        Cs[(r + 8) * CP + n]     = acc[nt][2];
        Cs[(r + 8) * CP + n + 1] = acc[nt][3];
    }
    __syncthreads();

    // --- coalesced store: fixed t, adjacent d per lane
    float* ob = out + (size_t)b * T_OUT * D_DIM + d0;
    for (int idx = tid; idx < CTA_ROWS * T_OUT; idx += THREADS) {
        int t = idx >> 6, i = idx & 63;
        ob[(size_t)t * D_DIM + i] = Cs[i * CP + t];
    }
}

extern "C" void kernel_launch(void* const* d_in, const int* in_sizes, int n_in,
                              void* d_out, int out_size) {
    const float* x  = (const float*)d_in[0];   // [256, 336, 512]
    const float* W  = (const float*)d_in[1];   // [24, 1]
    const float* bs = (const float*)d_in[2];   // [1]
    float* out = (float*)d_out;                // [256, 168, 512]

    ar_prep_kernel<<<1, 32>>>(W, bs);
    const int n_ctas = (B_DIM * D_DIM) / CTA_ROWS;   // 2048
    ar_mma_kernel<<<n_ctas, THREADS>>>(x, out);
}